// round 8
// baseline (speedup 1.0000x reference)
#include <cuda_runtime.h>
#include <cuda_fp16.h>
#include <cstdint>
#include <cstring>

#define Bsz 32
#define Ssz 4096
#define Dsz 1280
#define Rsz 64

// fp16 scratch: concatenated pre-rounded params + intermediate H
__device__ __half g_Acat[8 * 128 * Dsz];          // [e][n(128)][k(1280)]
__device__ __half g_Bcat[8 * Dsz * 128];          // [e][d(1280)][k(128)]
__device__ __half g_H[31u * Ssz * 128];           // [b][m][k(128)]

#define STGA 18432          // 128 rows x 144B (64 halves + pad)
#define STGH 34816          // 128 rows x 272B (128 halves + pad)
#define SMEM1 (2 * STGA + 3 * STGA)    // 92160
#define SMEM2 (STGH + 2 * STGH)        // 104448

// ---------------------------------------------------------------------------
__device__ __forceinline__ uint32_t smem_u32(const void* p) {
    uint32_t a;
    asm("{ .reg .u64 t; cvta.to.shared.u64 t, %1; cvt.u32.u64 %0, t; }" : "=r"(a) : "l"(p));
    return a;
}
__device__ __forceinline__ unsigned h2u(__half2 h) {
    unsigned u; memcpy(&u, &h, 4); return u;
}
__device__ __forceinline__ void cp16(uint32_t dst, const void* src) {
    asm volatile("cp.async.cg.shared.global [%0], [%1], 16;" :: "r"(dst), "l"(src));
}
__device__ __forceinline__ void commit_group() {
    asm volatile("cp.async.commit_group;" ::: "memory");
}
__device__ __forceinline__ void sts128(uint32_t a, unsigned u0, unsigned u1, unsigned u2, unsigned u3) {
    asm volatile("st.shared.v4.b32 [%0], {%1,%2,%3,%4};" :: "r"(a), "r"(u0), "r"(u1), "r"(u2), "r"(u3));
}
__device__ __forceinline__ void ldsm_x4(unsigned r[4], uint32_t addr) {
    asm volatile("ldmatrix.sync.aligned.m8n8.x4.shared.b16 {%0,%1,%2,%3}, [%4];"
                 : "=r"(r[0]), "=r"(r[1]), "=r"(r[2]), "=r"(r[3]) : "r"(addr));
}
__device__ __forceinline__ void mma16816(float c[4], const unsigned a[4], unsigned b0, unsigned b1) {
    asm volatile(
        "mma.sync.aligned.m16n8k16.row.col.f32.f16.f16.f32 "
        "{%0,%1,%2,%3}, {%4,%5,%6,%7}, {%8,%9}, {%0,%1,%2,%3};"
        : "+f"(c[0]), "+f"(c[1]), "+f"(c[2]), "+f"(c[3])
        : "r"(a[0]), "r"(a[1]), "r"(a[2]), "r"(a[3]), "r"(b0), "r"(b1));
}

// ---------------------------------------------------------------------------
// Pre-convert params to fp16 concatenated layouts (rn rounding).
// ---------------------------------------------------------------------------
__global__ void preconv_kernel(const float* __restrict__ A_exp,
                               const float* __restrict__ B_exp,
                               const float* __restrict__ A_gen,
                               const float* __restrict__ B_gen)
{
    int idx = blockIdx.x * blockDim.x + threadIdx.x;
    const int NA = 8 * 128 * Dsz / 2;
    if (idx < NA) {
        int p = idx * 2;
        int e = p / (128 * Dsz);
        int r = p % (128 * Dsz);
        int n = r / Dsz, k = r % Dsz;
        float f0, f1;
        if (n < Rsz) {
            const float* s = A_exp + ((size_t)e * Rsz + n) * Dsz + k;
            f0 = s[0]; f1 = s[1];
        } else {
            const float* s = A_gen + (size_t)(n - Rsz) * Dsz + k;
            f0 = s[0]; f1 = s[1];
        }
        *reinterpret_cast<__half2*>(&g_Acat[p]) = __floats2half2_rn(f0, f1);

        int e2 = p / (Dsz * 128);
        int r2 = p % (Dsz * 128);
        int d = r2 / 128, k2 = r2 % 128;
        float g0, g1;
        if (k2 < Rsz) {
            const float* s = B_exp + ((size_t)e2 * Dsz + d) * Rsz + k2;
            g0 = s[0]; g1 = s[1];
        } else {
            const float* s = B_gen + (size_t)d * Rsz + (k2 - Rsz);
            g0 = s[0]; g1 = s[1];
        }
        *reinterpret_cast<__half2*>(&g_Bcat[p]) = __floats2half2_rn(g0, g1);
    }
}

// ---------------------------------------------------------------------------
// GEMM1: H[b] (4096x128) = x[b] @ Acat[b]^T, fp16 mma, output fp16 to g_H.
// grid (32, 31), 512 thr (16 warps, 4Mx4N, warp tile 32x32). K-stage 64, KT=20.
// x producer decoupled: LDG+cvt one full iteration before its STS.
// ---------------------------------------------------------------------------
__global__ __launch_bounds__(512, 2) void gemm1_fp16(
    const float* __restrict__ x,
    const int*   __restrict__ label)
{
    extern __shared__ char smem[];
    const int b   = blockIdx.y;
    const int m0  = blockIdx.x * 128;
    const int e   = __ldg(&label[b]);
    const int tid = threadIdx.x;
    const int warp = tid >> 5, lane = tid & 31;
    const int wm = warp & 3, wn = (warp >> 2) & 3;
    const int lg = lane >> 2, lc = lane & 3;

    uint32_t sX = smem_u32(smem);                 // x ring: 2 stages
    uint32_t sA = sX + 2 * STGA;                  // Acat ring: 3 stages

    const char* xb = (const char*)(x + ((size_t)b * Ssz + m0) * Dsz);
    const char* Ab = (const char*)g_Acat + (size_t)e * 128 * Dsz * 2;

    // ldmatrix per-lane offsets (stride 144)
    uint32_t aoff[2], boff[2];
#pragma unroll
    for (int i = 0; i < 2; i++)
        aoff[i] = (uint32_t)((wm * 32 + i * 16 + (lane & 15)) * 144 + ((lane >> 4) << 4));
#pragma unroll
    for (int jp = 0; jp < 2; jp++)
        boff[jp] = (uint32_t)((wn * 32 + jp * 16 + (lane & 7) + ((lane >> 4) << 3)) * 144
                              + (((lane >> 3) & 1) << 4));

    auto cp_A = [&](int j) {
        uint32_t dst = sA + (j % 3) * STGA;
        const char* base = Ab + (size_t)j * 128;   // k-slice: 64 halves = 128B
#pragma unroll
        for (int i = 0; i < 2; i++) {
            int cid = tid + i * 512;               // 1024 chunks
            int row = cid >> 3, g = cid & 7;
            cp16(dst + row * 144 + g * 16, base + (size_t)row * (Dsz * 2) + g * 16);
        }
        commit_group();
    };

    // x pipeline regs: 8 half2 = one stage per thread (2 chunks of 16B fp16)
    unsigned xu[8];

    auto ldg_x = [&](int j) {
#pragma unroll
        for (int q = 0; q < 2; q++) {
            int cid = tid + q * 512;               // 1024 chunks
            int row = cid >> 3, gp = cid & 7;
            const float4* src = (const float4*)(xb + (size_t)row * (Dsz * 4) + j * 256 + gp * 32);
            float4 a = __ldg(src);
            float4 c = __ldg(src + 1);
            xu[q*4+0] = h2u(__floats2half2_rn(a.x, a.y));
            xu[q*4+1] = h2u(__floats2half2_rn(a.z, a.w));
            xu[q*4+2] = h2u(__floats2half2_rn(c.x, c.y));
            xu[q*4+3] = h2u(__floats2half2_rn(c.z, c.w));
        }
    };
    auto sts_x = [&](int j) {
        uint32_t dst = sX + (j & 1) * STGA;
#pragma unroll
        for (int q = 0; q < 2; q++) {
            int cid = tid + q * 512;
            int row = cid >> 3, gp = cid & 7;
            sts128(dst + row * 144 + gp * 16, xu[q*4+0], xu[q*4+1], xu[q*4+2], xu[q*4+3]);
        }
    };

    // prologue
    cp_A(0);
    cp_A(1);
    ldg_x(0);
    sts_x(0);
    ldg_x(1);          // in flight; STS'd at end of kt=0
    asm volatile("cp.async.wait_group 1;" ::: "memory");
    __syncthreads();

    float acc[2][4][4] = {};

    const int KT = Dsz / 64;    // 20
#pragma unroll 1
    for (int kt = 0; kt < KT; kt++) {
        if (kt + 2 < KT) cp_A(kt + 2);
        else             commit_group();

        uint32_t aS = sX + (kt & 1) * STGA;
        uint32_t bS = sA + (kt % 3) * STGA;

#pragma unroll
        for (int kk = 0; kk < 4; kk++) {
            unsigned af[2][4], bf[2][4];
            uint32_t kb = kk * 32;
#pragma unroll
            for (int i = 0; i < 2; i++) ldsm_x4(af[i], aS + aoff[i] + kb);
#pragma unroll
            for (int jp = 0; jp < 2; jp++) ldsm_x4(bf[jp], bS + boff[jp] + kb);
#pragma unroll
            for (int i = 0; i < 2; i++)
#pragma unroll
                for (int jp = 0; jp < 2; jp++) {
                    mma16816(acc[i][2*jp],   af[i], bf[jp][0], bf[jp][1]);
                    mma16816(acc[i][2*jp+1], af[i], bf[jp][2], bf[jp][3]);
                }
        }

        if (kt + 1 < KT) sts_x(kt + 1);
        if (kt + 2 < KT) ldg_x(kt + 2);

        asm volatile("cp.async.wait_group 1;" ::: "memory");
        __syncthreads();
    }

    // epilogue: H (fp16) -> global
    __half* Hb = g_H + ((size_t)b * Ssz + m0) * 128;
#pragma unroll
    for (int i = 0; i < 2; i++) {
        int r = wm * 32 + i * 16 + lg;
#pragma unroll
        for (int j = 0; j < 4; j++) {
            int c = wn * 32 + j * 8 + lc * 2;
            *reinterpret_cast<__half2*>(Hb + (size_t)r * 128 + c) =
                __floats2half2_rn(acc[i][j][0], acc[i][j][1]);
            *reinterpret_cast<__half2*>(Hb + (size_t)(r + 8) * 128 + c) =
                __floats2half2_rn(acc[i][j][2], acc[i][j][3]);
        }
    }
}

// ---------------------------------------------------------------------------
// GEMM2: out[b] (4096x1280) = 2 * H[b] @ Bcat[b]^T.
// grid (32, 32), 512 thr (16 warps, 4Mx4N, warp tile 32x32).
// H tile in smem once; loop 10 n-tiles, B ring 2 stages; B prefetch
// overlapped with epilogue stores. b==31 CTAs zero their slice.
// ---------------------------------------------------------------------------
__global__ __launch_bounds__(512, 2) void gemm2_fp16(
    const int* __restrict__ label,
    float*     __restrict__ out)
{
    extern __shared__ char smem[];
    const int b   = blockIdx.y;
    const int m0  = blockIdx.x * 128;
    const int tid = threadIdx.x;

    float* ob = out + ((size_t)b * Ssz + m0) * Dsz;

    if (b == Bsz - 1) {
        float4 z = make_float4(0.f, 0.f, 0.f, 0.f);
#pragma unroll 4
        for (int i = 0; i < 80; i++) {
            int v = tid + i * 512;       // 40960 float4 = 128 rows x 320
            int row = v / 320, c4 = v % 320;
            __stcs((float4*)(ob + (size_t)row * Dsz + c4 * 4), z);
        }
        return;
    }

    const int e = __ldg(&label[b]);
    const int warp = tid >> 5, lane = tid & 31;
    const int wm = warp & 3, wn = (warp >> 2) & 3;
    const int lg = lane >> 2, lc = lane & 3;

    uint32_t sH = smem_u32(smem);
    uint32_t sB = sH + STGH;

    // ldmatrix per-lane offsets (stride 272)
    uint32_t aoff[2], boff[2];
#pragma unroll
    for (int i = 0; i < 2; i++)
        aoff[i] = (uint32_t)((wm * 32 + i * 16 + (lane & 15)) * 272 + ((lane >> 4) << 4));
#pragma unroll
    for (int jp = 0; jp < 2; jp++)
        boff[jp] = (uint32_t)((wn * 32 + jp * 16 + (lane & 7) + ((lane >> 4) << 3)) * 272
                              + (((lane >> 3) & 1) << 4));

    // H tile load (once)
    {
        const char* base = (const char*)g_H + ((size_t)b * Ssz + m0) * 256;
#pragma unroll
        for (int i = 0; i < 4; i++) {
            int cid = tid + i * 512;               // 2048 chunks
            int row = cid >> 4, g = cid & 15;
            cp16(sH + row * 272 + g * 16, base + (size_t)row * 256 + g * 16);
        }
        commit_group();
    }

    auto cp_B = [&](int nt) {
        uint32_t dst = sB + (nt & 1) * STGH;
        const char* base = (const char*)g_Bcat + ((size_t)e * Dsz + nt * 128) * 256;
#pragma unroll
        for (int i = 0; i < 4; i++) {
            int cid = tid + i * 512;
            int row = cid >> 4, g = cid & 15;
            cp16(dst + row * 272 + g * 16, base + (size_t)row * 256 + g * 16);
        }
        commit_group();
    };

    cp_B(0);
    cp_B(1);
    asm volatile("cp.async.wait_group 1;" ::: "memory");   // H + B0 ready
    __syncthreads();

#pragma unroll 1
    for (int nt = 0; nt < 10; nt++) {
        float acc[2][4][4] = {};
        uint32_t bS = sB + (nt & 1) * STGH;

#pragma unroll
        for (int kk = 0; kk < 8; kk++) {
            unsigned af[2][4], bf[2][4];
            uint32_t kb = kk * 32;
#pragma unroll
            for (int i = 0; i < 2; i++) ldsm_x4(af[i], sH + aoff[i] + kb);
#pragma unroll
            for (int jp = 0; jp < 2; jp++) ldsm_x4(bf[jp], bS + boff[jp] + kb);
#pragma unroll
            for (int i = 0; i < 2; i++)
#pragma unroll
                for (int jp = 0; jp < 2; jp++) {
                    mma16816(acc[i][2*jp],   af[i], bf[jp][0], bf[jp][1]);
                    mma16816(acc[i][2*jp+1], af[i], bf[jp][2], bf[jp][3]);
                }
        }

        __syncthreads();                      // all warps done reading slot nt&1
        if (nt + 2 < 10) cp_B(nt + 2);        // refill freed slot, overlaps epilogue
        else             commit_group();

        // epilogue for this n-tile: out = 2*acc (hides B transfer)
        int n0 = nt * 128;
#pragma unroll
        for (int i = 0; i < 2; i++) {
            int r = wm * 32 + i * 16 + lg;
#pragma unroll
            for (int j = 0; j < 4; j++) {
                int c = n0 + wn * 32 + j * 8 + lc * 2;
                __stcs((float2*)&ob[(size_t)r * Dsz + c],
                       make_float2(2.0f * acc[i][j][0], 2.0f * acc[i][j][1]));
                __stcs((float2*)&ob[(size_t)(r + 8) * Dsz + c],
                       make_float2(2.0f * acc[i][j][2], 2.0f * acc[i][j][3]));
            }
        }

        asm volatile("cp.async.wait_group 1;" ::: "memory");   // B(nt+1) complete
        __syncthreads();
    }
}

// ---------------------------------------------------------------------------
extern "C" void kernel_launch(void* const* d_in, const int* in_sizes, int n_in,
                              void* d_out, int out_size)
{
    const float* x     = (const float*)d_in[0];
    // d_in[1] = weight : unused by the reference
    const float* A_exp = (const float*)d_in[2];
    const float* B_exp = (const float*)d_in[3];
    const float* A_gen = (const float*)d_in[4];
    const float* B_gen = (const float*)d_in[5];
    const int*   label = (const int*)d_in[6];
    float* out = (float*)d_out;

    cudaFuncSetAttribute(gemm1_fp16, cudaFuncAttributeMaxDynamicSharedMemorySize, SMEM1);
    cudaFuncSetAttribute(gemm2_fp16, cudaFuncAttributeMaxDynamicSharedMemorySize, SMEM2);

    preconv_kernel<<<(8 * 128 * Dsz / 2 + 255) / 256, 256>>>(A_exp, B_exp, A_gen, B_gen);
    gemm1_fp16<<<dim3(Ssz / 128, Bsz - 1), 512, SMEM1>>>(x, label);
    gemm2_fp16<<<dim3(Ssz / 128, Bsz), 512, SMEM2>>>(label, out);
}

// round 9
// speedup vs baseline: 1.0089x; 1.0089x over previous
#include <cuda_runtime.h>
#include <cuda_fp16.h>
#include <cstdint>
#include <cstring>

#define Bsz 32
#define Ssz 4096
#define Dsz 1280
#define Rsz 64

// fp16 scratch: concatenated pre-rounded params + intermediate H
__device__ __half g_Acat[8 * 128 * Dsz];          // [e][n(128)][k(1280)]
__device__ __half g_Bcat[8 * Dsz * 128];          // [e][d(1280)][k(128)]
__device__ __half g_H[31u * Ssz * 128];           // [b][m][k(128)]
__device__ int    g_flag[992];                    // per (b,m) H-ready flags

#define STGA 18432          // 128 rows x 144B (64 halves + pad)
#define STGH 34816          // 128 rows x 272B (128 halves + pad)
#define SMEM_FUSED (STGH + 2 * STGH)   // 104448 (>= phase-1's 92160)

#define NP1 992             // phase-1 CTAs (31 b x 32 m)
#define NP2 1024            // phase-2 CTAs (32 b x 32 m)

// ---------------------------------------------------------------------------
__device__ __forceinline__ uint32_t smem_u32(const void* p) {
    uint32_t a;
    asm("{ .reg .u64 t; cvta.to.shared.u64 t, %1; cvt.u32.u64 %0, t; }" : "=r"(a) : "l"(p));
    return a;
}
__device__ __forceinline__ unsigned h2u(__half2 h) {
    unsigned u; memcpy(&u, &h, 4); return u;
}
__device__ __forceinline__ void cp16(uint32_t dst, const void* src) {
    asm volatile("cp.async.cg.shared.global [%0], [%1], 16;" :: "r"(dst), "l"(src));
}
__device__ __forceinline__ void commit_group() {
    asm volatile("cp.async.commit_group;" ::: "memory");
}
__device__ __forceinline__ void sts128(uint32_t a, unsigned u0, unsigned u1, unsigned u2, unsigned u3) {
    asm volatile("st.shared.v4.b32 [%0], {%1,%2,%3,%4};" :: "r"(a), "r"(u0), "r"(u1), "r"(u2), "r"(u3));
}
__device__ __forceinline__ void ldsm_x4(unsigned r[4], uint32_t addr) {
    asm volatile("ldmatrix.sync.aligned.m8n8.x4.shared.b16 {%0,%1,%2,%3}, [%4];"
                 : "=r"(r[0]), "=r"(r[1]), "=r"(r[2]), "=r"(r[3]) : "r"(addr));
}
__device__ __forceinline__ void mma16816(float c[4], const unsigned a[4], unsigned b0, unsigned b1) {
    asm volatile(
        "mma.sync.aligned.m16n8k16.row.col.f32.f16.f16.f32 "
        "{%0,%1,%2,%3}, {%4,%5,%6,%7}, {%8,%9}, {%0,%1,%2,%3};"
        : "+f"(c[0]), "+f"(c[1]), "+f"(c[2]), "+f"(c[3])
        : "r"(a[0]), "r"(a[1]), "r"(a[2]), "r"(a[3]), "r"(b0), "r"(b1));
}

// ---------------------------------------------------------------------------
// Pre-convert params to fp16 concatenated layouts; reset H-ready flags.
// ---------------------------------------------------------------------------
__global__ void preconv_kernel(const float* __restrict__ A_exp,
                               const float* __restrict__ B_exp,
                               const float* __restrict__ A_gen,
                               const float* __restrict__ B_gen)
{
    int idx = blockIdx.x * blockDim.x + threadIdx.x;
    if (idx < NP1) g_flag[idx] = 0;
    const int NA = 8 * 128 * Dsz / 2;
    if (idx < NA) {
        int p = idx * 2;
        int e = p / (128 * Dsz);
        int r = p % (128 * Dsz);
        int n = r / Dsz, k = r % Dsz;
        float f0, f1;
        if (n < Rsz) {
            const float* s = A_exp + ((size_t)e * Rsz + n) * Dsz + k;
            f0 = s[0]; f1 = s[1];
        } else {
            const float* s = A_gen + (size_t)(n - Rsz) * Dsz + k;
            f0 = s[0]; f1 = s[1];
        }
        *reinterpret_cast<__half2*>(&g_Acat[p]) = __floats2half2_rn(f0, f1);

        int e2 = p / (Dsz * 128);
        int r2 = p % (Dsz * 128);
        int d = r2 / 128, k2 = r2 % 128;
        float g0, g1;
        if (k2 < Rsz) {
            const float* s = B_exp + ((size_t)e2 * Dsz + d) * Rsz + k2;
            g0 = s[0]; g1 = s[1];
        } else {
            const float* s = B_gen + (size_t)d * Rsz + (k2 - Rsz);
            g0 = s[0]; g1 = s[1];
        }
        *reinterpret_cast<__half2*>(&g_Bcat[p]) = __floats2half2_rn(g0, g1);
    }
}

// ---------------------------------------------------------------------------
// Fused two-phase kernel, linear grid NP1+NP2, 256 thr.
//  bid <  NP1 : phase 1 — H[b] m-tile = x_tile @ Acat[e]^T  (R7 gemm1 body)
//  bid >= NP1 : phase 2 — out m-tile = 2 * H_tile @ Bcat[e]^T (R7 gemm2 body),
//               spin-waits on the producer's flag; B prefetched during spin.
// ---------------------------------------------------------------------------
__global__ __launch_bounds__(256, 2) void fused_two_phase(
    const float* __restrict__ x,
    const int*   __restrict__ label,
    float*       __restrict__ out)
{
    extern __shared__ char smem[];
    const int bid = blockIdx.x;
    const int tid = threadIdx.x;
    const int warp = tid >> 5, lane = tid & 31;
    const int wm = warp & 3, wn = warp >> 2;
    const int lg = lane >> 2, lc = lane & 3;

    if (bid < NP1) {
        // ================= PHASE 1 =================
        const int b  = bid >> 5;
        const int m0 = (bid & 31) * 128;
        const int e  = __ldg(&label[b]);

        uint32_t sX = smem_u32(smem);
        uint32_t sA = sX + 2 * STGA;

        const char* xb = (const char*)(x + ((size_t)b * Ssz + m0) * Dsz);
        const char* Ab = (const char*)g_Acat + (size_t)e * 128 * Dsz * 2;

        uint32_t aoff[2], boff[4];
#pragma unroll
        for (int i = 0; i < 2; i++)
            aoff[i] = (uint32_t)((wm * 32 + i * 16 + (lane & 15)) * 144 + ((lane >> 4) << 4));
#pragma unroll
        for (int jp = 0; jp < 4; jp++)
            boff[jp] = (uint32_t)((wn * 64 + jp * 16 + (lane & 7) + ((lane >> 4) << 3)) * 144
                                  + (((lane >> 3) & 1) << 4));

        auto cp_A = [&](int j) {
            uint32_t dst = sA + (j % 3) * STGA;
            const char* base = Ab + (size_t)j * 128;
#pragma unroll
            for (int i = 0; i < 4; i++) {
                int cid = tid + i * 256;
                int row = cid >> 3, g = cid & 7;
                cp16(dst + row * 144 + g * 16, base + (size_t)row * (Dsz * 2) + g * 16);
            }
            commit_group();
        };

        unsigned xu[16];
        auto ldg_x = [&](int j) {
#pragma unroll
            for (int q = 0; q < 4; q++) {
                int cid = tid + q * 256;
                int row = cid >> 3, gp = cid & 7;
                const float4* src = (const float4*)(xb + (size_t)row * (Dsz * 4) + j * 256 + gp * 32);
                float4 a = __ldg(src);
                float4 c = __ldg(src + 1);
                xu[q*4+0] = h2u(__floats2half2_rn(a.x, a.y));
                xu[q*4+1] = h2u(__floats2half2_rn(a.z, a.w));
                xu[q*4+2] = h2u(__floats2half2_rn(c.x, c.y));
                xu[q*4+3] = h2u(__floats2half2_rn(c.z, c.w));
            }
        };
        auto sts_x = [&](int j) {
            uint32_t dst = sX + (j & 1) * STGA;
#pragma unroll
            for (int q = 0; q < 4; q++) {
                int cid = tid + q * 256;
                int row = cid >> 3, gp = cid & 7;
                sts128(dst + row * 144 + gp * 16, xu[q*4+0], xu[q*4+1], xu[q*4+2], xu[q*4+3]);
            }
        };

        cp_A(0);
        cp_A(1);
        ldg_x(0);
        sts_x(0);
        ldg_x(1);
        asm volatile("cp.async.wait_group 1;" ::: "memory");
        __syncthreads();

        float acc[2][8][4] = {};

        const int KT = Dsz / 64;    // 20
#pragma unroll 1
        for (int kt = 0; kt < KT; kt++) {
            if (kt + 2 < KT) cp_A(kt + 2);
            else             commit_group();

            uint32_t aS = sX + (kt & 1) * STGA;
            uint32_t bS = sA + (kt % 3) * STGA;

#pragma unroll
            for (int kk = 0; kk < 4; kk++) {
                unsigned af[2][4], bf[4][4];
                uint32_t kb = kk * 32;
#pragma unroll
                for (int i = 0; i < 2; i++) ldsm_x4(af[i], aS + aoff[i] + kb);
#pragma unroll
                for (int jp = 0; jp < 4; jp++) ldsm_x4(bf[jp], bS + boff[jp] + kb);
#pragma unroll
                for (int i = 0; i < 2; i++)
#pragma unroll
                    for (int jp = 0; jp < 4; jp++) {
                        mma16816(acc[i][2*jp],   af[i], bf[jp][0], bf[jp][1]);
                        mma16816(acc[i][2*jp+1], af[i], bf[jp][2], bf[jp][3]);
                    }
            }

            if (kt + 1 < KT) sts_x(kt + 1);
            if (kt + 2 < KT) ldg_x(kt + 2);

            asm volatile("cp.async.wait_group 1;" ::: "memory");
            __syncthreads();
        }

        // epilogue: H (fp16) -> global, then signal
        __half* Hb = g_H + ((size_t)b * Ssz + m0) * 128;
#pragma unroll
        for (int i = 0; i < 2; i++) {
            int r = wm * 32 + i * 16 + lg;
#pragma unroll
            for (int j = 0; j < 8; j++) {
                int c = wn * 64 + j * 8 + lc * 2;
                *reinterpret_cast<__half2*>(Hb + (size_t)r * 128 + c) =
                    __floats2half2_rn(acc[i][j][0], acc[i][j][1]);
                *reinterpret_cast<__half2*>(Hb + (size_t)(r + 8) * 128 + c) =
                    __floats2half2_rn(acc[i][j][2], acc[i][j][3]);
            }
        }
        __syncthreads();
        if (tid == 0) {
            __threadfence();
            *(volatile int*)&g_flag[bid] = 1;
        }
        return;
    }

    // ================= PHASE 2 =================
    const int p  = bid - NP1;
    const int b  = p >> 5;
    const int m0 = (p & 31) * 128;

    float* ob = out + ((size_t)b * Ssz + m0) * Dsz;

    if (b == Bsz - 1) {
        float4 z = make_float4(0.f, 0.f, 0.f, 0.f);
#pragma unroll 4
        for (int i = 0; i < 160; i++) {
            int v = tid + i * 256;       // 40960 float4 = 128 rows x 320
            int row = v / 320, c4 = v % 320;
            __stcs((float4*)(ob + (size_t)row * Dsz + c4 * 4), z);
        }
        return;
    }

    const int e = __ldg(&label[b]);

    uint32_t sH = smem_u32(smem);
    uint32_t sB = sH + STGH;

    uint32_t aoff[2], boff[4];
#pragma unroll
    for (int i = 0; i < 2; i++)
        aoff[i] = (uint32_t)((wm * 32 + i * 16 + (lane & 15)) * 272 + ((lane >> 4) << 4));
#pragma unroll
    for (int jp = 0; jp < 4; jp++)
        boff[jp] = (uint32_t)((wn * 64 + jp * 16 + (lane & 7) + ((lane >> 4) << 3)) * 272
                              + (((lane >> 3) & 1) << 4));

    auto cp_B = [&](int nt) {
        uint32_t dst = sB + (nt & 1) * STGH;
        const char* base = (const char*)g_Bcat + ((size_t)e * Dsz + nt * 128) * 256;
#pragma unroll
        for (int i = 0; i < 8; i++) {
            int cid = tid + i * 256;
            int row = cid >> 4, g = cid & 15;
            cp16(dst + row * 272 + g * 16, base + (size_t)row * 256 + g * 16);
        }
        commit_group();
    };

    // B tiles do not depend on H: prefetch them while waiting for the producer.
    cp_B(0);
    cp_B(1);

    if (tid == 0) {
        volatile int* f = &g_flag[p];
        while (*f == 0) __nanosleep(64);
        __threadfence();
    }
    __syncthreads();

    // H tile load (producer done)
    {
        const char* base = (const char*)g_H + ((size_t)b * Ssz + m0) * 256;
#pragma unroll
        for (int i = 0; i < 8; i++) {
            int cid = tid + i * 256;
            int row = cid >> 4, g = cid & 15;
            cp16(sH + row * 272 + g * 16, base + (size_t)row * 256 + g * 16);
        }
        commit_group();
    }

    asm volatile("cp.async.wait_group 0;" ::: "memory");   // B0 + B1 + H ready
    __syncthreads();

#pragma unroll 1
    for (int nt = 0; nt < 10; nt++) {
        float acc[2][8][4] = {};
        uint32_t bS = sB + (nt & 1) * STGH;

#pragma unroll
        for (int kk = 0; kk < 8; kk++) {
            unsigned af[2][4], bf[4][4];
            uint32_t kb = kk * 32;
#pragma unroll
            for (int i = 0; i < 2; i++) ldsm_x4(af[i], sH + aoff[i] + kb);
#pragma unroll
            for (int jp = 0; jp < 4; jp++) ldsm_x4(bf[jp], bS + boff[jp] + kb);
#pragma unroll
            for (int i = 0; i < 2; i++)
#pragma unroll
                for (int jp = 0; jp < 4; jp++) {
                    mma16816(acc[i][2*jp],   af[i], bf[jp][0], bf[jp][1]);
                    mma16816(acc[i][2*jp+1], af[i], bf[jp][2], bf[jp][3]);
                }
        }

        __syncthreads();                      // all warps done reading slot nt&1
        if (nt + 2 < 10) cp_B(nt + 2);        // refill freed slot, overlaps epilogue
        else             commit_group();

        int n0 = nt * 128;
#pragma unroll
        for (int i = 0; i < 2; i++) {
            int r = wm * 32 + i * 16 + lg;
#pragma unroll
            for (int j = 0; j < 8; j++) {
                int c = n0 + wn * 64 + j * 8 + lc * 2;
                __stcs((float2*)&ob[(size_t)r * Dsz + c],
                       make_float2(2.0f * acc[i][j][0], 2.0f * acc[i][j][1]));
                __stcs((float2*)&ob[(size_t)(r + 8) * Dsz + c],
                       make_float2(2.0f * acc[i][j][2], 2.0f * acc[i][j][3]));
            }
        }

        asm volatile("cp.async.wait_group 1;" ::: "memory");   // B(nt+1) complete
        __syncthreads();
    }
}

// ---------------------------------------------------------------------------
extern "C" void kernel_launch(void* const* d_in, const int* in_sizes, int n_in,
                              void* d_out, int out_size)
{
    const float* x     = (const float*)d_in[0];
    // d_in[1] = weight : unused by the reference
    const float* A_exp = (const float*)d_in[2];
    const float* B_exp = (const float*)d_in[3];
    const float* A_gen = (const float*)d_in[4];
    const float* B_gen = (const float*)d_in[5];
    const int*   label = (const int*)d_in[6];
    float* out = (float*)d_out;

    cudaFuncSetAttribute(fused_two_phase, cudaFuncAttributeMaxDynamicSharedMemorySize, SMEM_FUSED);

    preconv_kernel<<<(8 * 128 * Dsz / 2 + 255) / 256, 256>>>(A_exp, B_exp, A_gen, B_gen);
    fused_two_phase<<<NP1 + NP2, 256, SMEM_FUSED>>>(x, label, out);
}

// round 10
// speedup vs baseline: 1.0128x; 1.0039x over previous
#include <cuda_runtime.h>
#include <cuda_fp16.h>
#include <cstdint>
#include <cstring>

#define Bsz 32
#define Ssz 4096
#define Dsz 1280
#define Rsz 64

// fp16 scratch: concatenated pre-rounded params + intermediate H
__device__ __half g_Acat[8 * 128 * Dsz];          // [e][n(128)][k(1280)]
__device__ __half g_Bcat[8 * Dsz * 128];          // [e][d(1280)][k(128)]
__device__ __half g_H[31u * Ssz * 128];           // [b][m][k(128)]
__device__ int    g_flag[992];                    // per (b,m) H-ready flags
__device__ int    g_ctr;                          // persistent work counter

#define STGA 18432          // 128 rows x 144B (64 halves + pad)
#define STGH 34816          // 128 rows x 272B (128 halves + pad)
#define SMEM_FUSED (STGH + 2 * STGH)   // 104448 (>= phase-1's 92160)

#define NP1 992             // phase-1 items (31 b x 32 m)
#define NP2 1024            // phase-2 items (32 b x 32 m)
#define NITEMS (NP1 + NP2)

// ---------------------------------------------------------------------------
__device__ __forceinline__ uint32_t smem_u32(const void* p) {
    uint32_t a;
    asm("{ .reg .u64 t; cvta.to.shared.u64 t, %1; cvt.u32.u64 %0, t; }" : "=r"(a) : "l"(p));
    return a;
}
__device__ __forceinline__ unsigned h2u(__half2 h) {
    unsigned u; memcpy(&u, &h, 4); return u;
}
__device__ __forceinline__ void cp16(uint32_t dst, const void* src) {
    asm volatile("cp.async.cg.shared.global [%0], [%1], 16;" :: "r"(dst), "l"(src));
}
__device__ __forceinline__ void commit_group() {
    asm volatile("cp.async.commit_group;" ::: "memory");
}
__device__ __forceinline__ void sts128(uint32_t a, unsigned u0, unsigned u1, unsigned u2, unsigned u3) {
    asm volatile("st.shared.v4.b32 [%0], {%1,%2,%3,%4};" :: "r"(a), "r"(u0), "r"(u1), "r"(u2), "r"(u3));
}
__device__ __forceinline__ void ldsm_x4(unsigned r[4], uint32_t addr) {
    asm volatile("ldmatrix.sync.aligned.m8n8.x4.shared.b16 {%0,%1,%2,%3}, [%4];"
                 : "=r"(r[0]), "=r"(r[1]), "=r"(r[2]), "=r"(r[3]) : "r"(addr));
}
__device__ __forceinline__ void mma16816(float c[4], const unsigned a[4], unsigned b0, unsigned b1) {
    asm volatile(
        "mma.sync.aligned.m16n8k16.row.col.f32.f16.f16.f32 "
        "{%0,%1,%2,%3}, {%4,%5,%6,%7}, {%8,%9}, {%0,%1,%2,%3};"
        : "+f"(c[0]), "+f"(c[1]), "+f"(c[2]), "+f"(c[3])
        : "r"(a[0]), "r"(a[1]), "r"(a[2]), "r"(a[3]), "r"(b0), "r"(b1));
}

// ---------------------------------------------------------------------------
// Pre-convert params to fp16 concatenated layouts; reset flags + work counter.
// ---------------------------------------------------------------------------
__global__ void preconv_kernel(const float* __restrict__ A_exp,
                               const float* __restrict__ B_exp,
                               const float* __restrict__ A_gen,
                               const float* __restrict__ B_gen)
{
    int idx = blockIdx.x * blockDim.x + threadIdx.x;
    if (idx == 0) g_ctr = 0;
    if (idx < NP1) g_flag[idx] = 0;
    const int NA = 8 * 128 * Dsz / 2;
    if (idx < NA) {
        int p = idx * 2;
        int e = p / (128 * Dsz);
        int r = p % (128 * Dsz);
        int n = r / Dsz, k = r % Dsz;
        float f0, f1;
        if (n < Rsz) {
            const float* s = A_exp + ((size_t)e * Rsz + n) * Dsz + k;
            f0 = s[0]; f1 = s[1];
        } else {
            const float* s = A_gen + (size_t)(n - Rsz) * Dsz + k;
            f0 = s[0]; f1 = s[1];
        }
        *reinterpret_cast<__half2*>(&g_Acat[p]) = __floats2half2_rn(f0, f1);

        int e2 = p / (Dsz * 128);
        int r2 = p % (Dsz * 128);
        int d = r2 / 128, k2 = r2 % 128;
        float g0, g1;
        if (k2 < Rsz) {
            const float* s = B_exp + ((size_t)e2 * Dsz + d) * Rsz + k2;
            g0 = s[0]; g1 = s[1];
        } else {
            const float* s = B_gen + (size_t)d * Rsz + (k2 - Rsz);
            g0 = s[0]; g1 = s[1];
        }
        *reinterpret_cast<__half2*>(&g_Bcat[p]) = __floats2half2_rn(g0, g1);
    }
}

// ---------------------------------------------------------------------------
// Persistent two-phase kernel. grid = 2*SMs CTAs, 256 thr.
// Work items via atomicAdd: [0,NP1) = gemm1 tiles, [NP1,NP1+NP2) = gemm2 tiles.
// All producers are grabbed before any consumer => a spinning consumer's
// producer is always running or done (deadlock-free, near-zero spin).
// ---------------------------------------------------------------------------
__global__ __launch_bounds__(256, 2) void persist_two_phase(
    const float* __restrict__ x,
    const int*   __restrict__ label,
    float*       __restrict__ out)
{
    extern __shared__ char smem[];
    __shared__ int s_item;
    const int tid = threadIdx.x;
    const int warp = tid >> 5, lane = tid & 31;
    const int wm = warp & 3, wn = warp >> 2;
    const int lg = lane >> 2, lc = lane & 3;

    for (;;) {
        __syncthreads();                       // previous item fully done with smem
        if (tid == 0) s_item = atomicAdd(&g_ctr, 1);
        __syncthreads();
        const int item = s_item;
        if (item >= NITEMS) break;

        if (item < NP1) {
            // ================= PHASE 1 =================
            const int b  = item >> 5;
            const int m0 = (item & 31) * 128;
            const int e  = __ldg(&label[b]);

            uint32_t sX = smem_u32(smem);
            uint32_t sA = sX + 2 * STGA;

            const char* xb = (const char*)(x + ((size_t)b * Ssz + m0) * Dsz);
            const char* Ab = (const char*)g_Acat + (size_t)e * 128 * Dsz * 2;

            uint32_t aoff[2], boff[4];
#pragma unroll
            for (int i = 0; i < 2; i++)
                aoff[i] = (uint32_t)((wm * 32 + i * 16 + (lane & 15)) * 144 + ((lane >> 4) << 4));
#pragma unroll
            for (int jp = 0; jp < 4; jp++)
                boff[jp] = (uint32_t)((wn * 64 + jp * 16 + (lane & 7) + ((lane >> 4) << 3)) * 144
                                      + (((lane >> 3) & 1) << 4));

            auto cp_A = [&](int j) {
                uint32_t dst = sA + (j % 3) * STGA;
                const char* base = Ab + (size_t)j * 128;
#pragma unroll
                for (int i = 0; i < 4; i++) {
                    int cid = tid + i * 256;
                    int row = cid >> 3, g = cid & 7;
                    cp16(dst + row * 144 + g * 16, base + (size_t)row * (Dsz * 2) + g * 16);
                }
                commit_group();
            };

            unsigned xu[16];
            auto ldg_x = [&](int j) {
#pragma unroll
                for (int q = 0; q < 4; q++) {
                    int cid = tid + q * 256;
                    int row = cid >> 3, gp = cid & 7;
                    const float4* src = (const float4*)(xb + (size_t)row * (Dsz * 4) + j * 256 + gp * 32);
                    float4 a = __ldg(src);
                    float4 c = __ldg(src + 1);
                    xu[q*4+0] = h2u(__floats2half2_rn(a.x, a.y));
                    xu[q*4+1] = h2u(__floats2half2_rn(a.z, a.w));
                    xu[q*4+2] = h2u(__floats2half2_rn(c.x, c.y));
                    xu[q*4+3] = h2u(__floats2half2_rn(c.z, c.w));
                }
            };
            auto sts_x = [&](int j) {
                uint32_t dst = sX + (j & 1) * STGA;
#pragma unroll
                for (int q = 0; q < 4; q++) {
                    int cid = tid + q * 256;
                    int row = cid >> 3, gp = cid & 7;
                    sts128(dst + row * 144 + gp * 16, xu[q*4+0], xu[q*4+1], xu[q*4+2], xu[q*4+3]);
                }
            };

            cp_A(0);
            cp_A(1);
            ldg_x(0);
            sts_x(0);
            ldg_x(1);
            asm volatile("cp.async.wait_group 1;" ::: "memory");
            __syncthreads();

            float acc[2][8][4] = {};

            const int KT = Dsz / 64;    // 20
#pragma unroll 1
            for (int kt = 0; kt < KT; kt++) {
                if (kt + 2 < KT) cp_A(kt + 2);
                else             commit_group();

                uint32_t aS = sX + (kt & 1) * STGA;
                uint32_t bS = sA + (kt % 3) * STGA;

#pragma unroll
                for (int kk = 0; kk < 4; kk++) {
                    unsigned af[2][4], bf[4][4];
                    uint32_t kb = kk * 32;
#pragma unroll
                    for (int i = 0; i < 2; i++) ldsm_x4(af[i], aS + aoff[i] + kb);
#pragma unroll
                    for (int jp = 0; jp < 4; jp++) ldsm_x4(bf[jp], bS + boff[jp] + kb);
#pragma unroll
                    for (int i = 0; i < 2; i++)
#pragma unroll
                        for (int jp = 0; jp < 4; jp++) {
                            mma16816(acc[i][2*jp],   af[i], bf[jp][0], bf[jp][1]);
                            mma16816(acc[i][2*jp+1], af[i], bf[jp][2], bf[jp][3]);
                        }
                }

                if (kt + 1 < KT) sts_x(kt + 1);
                if (kt + 2 < KT) ldg_x(kt + 2);

                asm volatile("cp.async.wait_group 1;" ::: "memory");
                __syncthreads();
            }
            asm volatile("cp.async.wait_group 0;" ::: "memory");

            // epilogue: H (fp16) -> global, then signal
            __half* Hb = g_H + ((size_t)b * Ssz + m0) * 128;
#pragma unroll
            for (int i = 0; i < 2; i++) {
                int r = wm * 32 + i * 16 + lg;
#pragma unroll
                for (int j = 0; j < 8; j++) {
                    int c = wn * 64 + j * 8 + lc * 2;
                    *reinterpret_cast<__half2*>(Hb + (size_t)r * 128 + c) =
                        __floats2half2_rn(acc[i][j][0], acc[i][j][1]);
                    *reinterpret_cast<__half2*>(Hb + (size_t)(r + 8) * 128 + c) =
                        __floats2half2_rn(acc[i][j][2], acc[i][j][3]);
                }
            }
            __syncthreads();
            if (tid == 0) {
                __threadfence();
                *(volatile int*)&g_flag[item] = 1;
            }
            continue;
        }

        // ================= PHASE 2 =================
        {
            const int p  = item - NP1;
            const int b  = p >> 5;
            const int m0 = (p & 31) * 128;

            float* ob = out + ((size_t)b * Ssz + m0) * Dsz;

            if (b == Bsz - 1) {
                float4 z = make_float4(0.f, 0.f, 0.f, 0.f);
#pragma unroll 4
                for (int i = 0; i < 160; i++) {
                    int v = tid + i * 256;       // 40960 float4 = 128 rows x 320
                    int row = v / 320, c4 = v % 320;
                    __stcs((float4*)(ob + (size_t)row * Dsz + c4 * 4), z);
                }
                continue;
            }

            const int e = __ldg(&label[b]);

            uint32_t sH = smem_u32(smem);
            uint32_t sB = sH + STGH;

            uint32_t aoff[2], boff[4];
#pragma unroll
            for (int i = 0; i < 2; i++)
                aoff[i] = (uint32_t)((wm * 32 + i * 16 + (lane & 15)) * 272 + ((lane >> 4) << 4));
#pragma unroll
            for (int jp = 0; jp < 4; jp++)
                boff[jp] = (uint32_t)((wn * 64 + jp * 16 + (lane & 7) + ((lane >> 4) << 3)) * 272
                                      + (((lane >> 3) & 1) << 4));

            auto cp_B = [&](int nt) {
                uint32_t dst = sB + (nt & 1) * STGH;
                const char* base = (const char*)g_Bcat + ((size_t)e * Dsz + nt * 128) * 256;
#pragma unroll
                for (int i = 0; i < 8; i++) {
                    int cid = tid + i * 256;
                    int row = cid >> 4, g = cid & 15;
                    cp16(dst + row * 272 + g * 16, base + (size_t)row * 256 + g * 16);
                }
                commit_group();
            };

            // B tiles don't depend on H: prefetch during (short) wait.
            cp_B(0);
            cp_B(1);

            if (tid == 0) {
                volatile int* f = &g_flag[p];
                while (*f == 0) __nanosleep(64);
                __threadfence();
            }
            __syncthreads();

            // H tile load (producer done)
            {
                const char* base = (const char*)g_H + ((size_t)b * Ssz + m0) * 256;
#pragma unroll
                for (int i = 0; i < 8; i++) {
                    int cid = tid + i * 256;
                    int row = cid >> 4, g = cid & 15;
                    cp16(sH + row * 272 + g * 16, base + (size_t)row * 256 + g * 16);
                }
                commit_group();
            }

            asm volatile("cp.async.wait_group 0;" ::: "memory");   // B0 + B1 + H ready
            __syncthreads();

#pragma unroll 1
            for (int nt = 0; nt < 10; nt++) {
                float acc[2][8][4] = {};
                uint32_t bS = sB + (nt & 1) * STGH;

#pragma unroll
                for (int kk = 0; kk < 8; kk++) {
                    unsigned af[2][4], bf[4][4];
                    uint32_t kb = kk * 32;
#pragma unroll
                    for (int i = 0; i < 2; i++) ldsm_x4(af[i], sH + aoff[i] + kb);
#pragma unroll
                    for (int jp = 0; jp < 4; jp++) ldsm_x4(bf[jp], bS + boff[jp] + kb);
#pragma unroll
                    for (int i = 0; i < 2; i++)
#pragma unroll
                        for (int jp = 0; jp < 4; jp++) {
                            mma16816(acc[i][2*jp],   af[i], bf[jp][0], bf[jp][1]);
                            mma16816(acc[i][2*jp+1], af[i], bf[jp][2], bf[jp][3]);
                        }
                }

                __syncthreads();                      // warps done reading slot nt&1
                if (nt + 2 < 10) cp_B(nt + 2);        // refill, overlaps epilogue
                else             commit_group();

                int n0 = nt * 128;
#pragma unroll
                for (int i = 0; i < 2; i++) {
                    int r = wm * 32 + i * 16 + lg;
#pragma unroll
                    for (int j = 0; j < 8; j++) {
                        int c = n0 + wn * 64 + j * 8 + lc * 2;
                        __stcs((float2*)&ob[(size_t)r * Dsz + c],
                               make_float2(2.0f * acc[i][j][0], 2.0f * acc[i][j][1]));
                        __stcs((float2*)&ob[(size_t)(r + 8) * Dsz + c],
                               make_float2(2.0f * acc[i][j][2], 2.0f * acc[i][j][3]));
                    }
                }

                asm volatile("cp.async.wait_group 1;" ::: "memory");   // B(nt+1) done
                __syncthreads();
            }
            asm volatile("cp.async.wait_group 0;" ::: "memory");
        }
    }
}

// ---------------------------------------------------------------------------
extern "C" void kernel_launch(void* const* d_in, const int* in_sizes, int n_in,
                              void* d_out, int out_size)
{
    const float* x     = (const float*)d_in[0];
    // d_in[1] = weight : unused by the reference
    const float* A_exp = (const float*)d_in[2];
    const float* B_exp = (const float*)d_in[3];
    const float* A_gen = (const float*)d_in[4];
    const float* B_gen = (const float*)d_in[5];
    const int*   label = (const int*)d_in[6];
    float* out = (float*)d_out;

    static int nsm = 0;
    if (!nsm) {
        cudaDeviceGetAttribute(&nsm, cudaDevAttrMultiProcessorCount, 0);
        cudaFuncSetAttribute(persist_two_phase,
                             cudaFuncAttributeMaxDynamicSharedMemorySize, SMEM_FUSED);
    }

    preconv_kernel<<<(8 * 128 * Dsz / 2 + 255) / 256, 256>>>(A_exp, B_exp, A_gen, B_gen);
    persist_two_phase<<<2 * nsm, 256, SMEM_FUSED>>>(x, label, out);
}